// round 1
// baseline (speedup 1.0000x reference)
#include <cuda_runtime.h>
#include <cstdint>

#define N_SEQ 16384
#define S 128

// Scratch (device globals: allocation-free per harness rules)
__device__ float g_x[N_SEQ * S];        // 8 MB
__device__ float g_gi[N_SEQ * 3 * S];   // 25 MB

// ---------------------------------------------------------------------------
// fast-math helpers (MUFU-backed)
// ---------------------------------------------------------------------------
__device__ __forceinline__ float ex2f(float x) {
    float y; asm("ex2.approx.f32 %0, %1;" : "=f"(y) : "f"(x)); return y;
}
__device__ __forceinline__ float rcpf(float x) {
    float y; asm("rcp.approx.f32 %0, %1;" : "=f"(y) : "f"(x)); return y;
}
__device__ __forceinline__ float sigmoidf_(float x) {
    // 1/(1+exp(-x)) = rcp(1 + 2^(-x*log2e))
    return rcpf(1.0f + ex2f(-1.4426950408889634f * x));
}
__device__ __forceinline__ float tanhf_(float x) {
    // tanh(x) = 2*sigmoid(2x) - 1
    return fmaf(2.0f, rcpf(1.0f + ex2f(-2.8853900817779268f * x)), -1.0f);
}

// ---------------------------------------------------------------------------
// packed f32x2 FMA (Blackwell): 2 lane-FMAs per issue
// ---------------------------------------------------------------------------
__device__ __forceinline__ unsigned long long pack2(float a, float b) {
    unsigned long long r;
    asm("mov.b64 %0, {%1, %2};" : "=l"(r) : "f"(a), "f"(b));
    return r;
}
__device__ __forceinline__ void fma2(unsigned long long& d,
                                     unsigned long long a, unsigned long long b) {
    asm("fma.rn.f32x2 %0, %1, %2, %0;" : "+l"(d) : "l"(a), "l"(b));
}
__device__ __forceinline__ float2 unpack2(unsigned long long v) {
    float lo, hi;
    asm("mov.b64 {%0, %1}, %2;" : "=f"(lo), "=f"(hi) : "l"(v));
    return make_float2(lo, hi);
}

// ---------------------------------------------------------------------------
// Prelude: Y[n][j] = dot(X[n], W[j]) + b[j]   (W rows are length 128)
// maskcol >= 0: that output column is the one-hot mask (1 at row 0) instead.
// 256 threads/block; block covers a 64-wide j-tile x 128-row tile.
// ---------------------------------------------------------------------------
__device__ __forceinline__ void dense_body(
    const float* __restrict__ X, const float* __restrict__ W,
    const float* __restrict__ b, float* __restrict__ Y,
    int J, int maskcol)
{
    __shared__ float wt[64 * 132];
    __shared__ float bs[64];
    __shared__ __align__(16) float xs[2][S];

    const int jbase = blockIdx.x * 64;
    const int rbase = blockIdx.y * 128;

    for (int idx = threadIdx.x; idx < 64 * S; idx += 256) {
        int j = idx >> 7, k = idx & 127;
        int gj = jbase + j;
        float v = 0.0f;
        if (gj < J && gj != maskcol) v = W[gj * S + k];
        wt[j * 132 + k] = v;
    }
    if (threadIdx.x < 64) {
        int gj = jbase + threadIdx.x;
        bs[threadIdx.x] = (gj < J && gj != maskcol) ? b[gj] : 0.0f;
    }
    __syncthreads();

    const int j = threadIdx.x >> 2;   // 0..63
    const int q = threadIdx.x & 3;    // k-quarter (strided k = 4i+q: conflict-free)

    for (int r0 = 0; r0 < 128; r0 += 2) {
        {
            int rr = threadIdx.x >> 7, k = threadIdx.x & 127;
            xs[rr][k] = X[(rbase + r0 + rr) * S + k];
        }
        __syncthreads();

        float a0 = 0.0f, a1 = 0.0f;
#pragma unroll
        for (int i = 0; i < 32; i++) {
            int k = 4 * i + q;
            float w = wt[j * 132 + k];
            a0 = fmaf(w, xs[0][k], a0);
            a1 = fmaf(w, xs[1][k], a1);
        }
        a0 += __shfl_xor_sync(0xffffffffu, a0, 1);
        a0 += __shfl_xor_sync(0xffffffffu, a0, 2);
        a1 += __shfl_xor_sync(0xffffffffu, a1, 1);
        a1 += __shfl_xor_sync(0xffffffffu, a1, 2);

        if (q == 0) {
            int gj = jbase + j;
            if (gj < J) {
                int row0 = rbase + r0;
                float v0 = a0 + bs[j];
                float v1 = a1 + bs[j];
                if (gj == maskcol) { v0 = (row0 == 0) ? 1.0f : 0.0f; v1 = 0.0f; }
                Y[row0 * J + gj]       = v0;
                Y[(row0 + 1) * J + gj] = v1;
            }
        }
        __syncthreads();
    }
}

__global__ void proj_kernel(const float* __restrict__ evs,
                            const float* __restrict__ proj_w,
                            const float* __restrict__ proj_b)
{
    dense_body(evs, proj_w, proj_b, g_x, S, 127);
}

__global__ void ih_kernel(const float* __restrict__ w_ih,
                          const float* __restrict__ b_ih)
{
    dense_body(g_x, w_ih, b_ih, g_gi, 3 * S, -1);
}

// ---------------------------------------------------------------------------
// The sequential GRU scan. One CTA, 512 threads.
// Thread (u = tid>>2, q = tid&3) owns W_hh rows {u, 128+u, 256+u},
// k in [32q, 32q+32), held in registers as 48 packed f32x2 values.
// ---------------------------------------------------------------------------
__global__ void __launch_bounds__(512, 1)
gru_scan_kernel(const float* __restrict__ w_hh, const float* __restrict__ b_hh,
                const float* __restrict__ h0,   const float* __restrict__ fw,
                const float* __restrict__ fb,   float* __restrict__ out)
{
    __shared__ __align__(16) float  h_s[S];
    __shared__ __align__(16) float4 gh4[S];

    const int tid = threadIdx.x;
    const int u = tid >> 2;
    const int q = tid & 3;

    // W_hh slice -> registers (packed pairs)
    unsigned long long w0[16], w1[16], w2[16];
    const float2* Wr = reinterpret_cast<const float2*>(w_hh);  // 64 float2 per row
#pragma unroll
    for (int i = 0; i < 16; i++) {
        float2 a = Wr[(u)         * 64 + q * 16 + i];
        float2 c = Wr[(S + u)     * 64 + q * 16 + i];
        float2 d = Wr[(2 * S + u) * 64 + q * 16 + i];
        w0[i] = pack2(a.x, a.y);
        w1[i] = pack2(c.x, c.y);
        w2[i] = pack2(d.x, d.y);
    }

    float br = 0.0f, bz = 0.0f, bn = 0.0f, hprev = 0.0f;
    if (tid < S) {
        br = b_hh[tid];
        bz = b_hh[S + tid];
        bn = b_hh[2 * S + tid];
        hprev = h0[tid];
        h_s[tid] = hprev;
    }
    __syncthreads();

    const unsigned long long* h8 = reinterpret_cast<const unsigned long long*>(h_s);
    const float* __restrict__ gi = g_gi;

    for (int t = 0; t < N_SEQ; t++) {
        // Prefetch this step's input projections (latency hidden under matvec).
        float gr = 0.0f, gz = 0.0f, gn = 0.0f;
        if (tid < S) {
            const float* gp = gi + t * (3 * S) + tid;
            gr = __ldg(gp);
            gz = __ldg(gp + S);
            gn = __ldg(gp + 2 * S);
        }

        // matvec: gh = W_hh @ h (partial over this thread's 32 k's, 3 rows)
        unsigned long long a0 = 0ull, a1 = 0ull, a2 = 0ull;
#pragma unroll
        for (int i = 0; i < 8; i++) {
            unsigned long long hA = h8[q * 16 + 2 * i];
            unsigned long long hB = h8[q * 16 + 2 * i + 1];
            fma2(a0, w0[2 * i], hA); fma2(a0, w0[2 * i + 1], hB);
            fma2(a1, w1[2 * i], hA); fma2(a1, w1[2 * i + 1], hB);
            fma2(a2, w2[2 * i], hA); fma2(a2, w2[2 * i + 1], hB);
        }
        float2 f0 = unpack2(a0), f1 = unpack2(a1), f2 = unpack2(a2);
        float rs = f0.x + f0.y;
        float zs = f1.x + f1.y;
        float ns = f2.x + f2.y;
        // reduce across the 4 adjacent q-lanes
        rs += __shfl_xor_sync(0xffffffffu, rs, 1);
        rs += __shfl_xor_sync(0xffffffffu, rs, 2);
        zs += __shfl_xor_sync(0xffffffffu, zs, 1);
        zs += __shfl_xor_sync(0xffffffffu, zs, 2);
        ns += __shfl_xor_sync(0xffffffffu, ns, 1);
        ns += __shfl_xor_sync(0xffffffffu, ns, 2);
        if (q == 0) gh4[u] = make_float4(rs, zs, ns, 0.0f);
        __syncthreads();

        // gates: warps 0-3 only (one per SMSP -> MUFU spread)
        if (tid < S) {
            float4 s = gh4[tid];
            float r = sigmoidf_(gr + s.x + br);
            float z = sigmoidf_(gz + s.y + bz);
            float n = tanhf_(fmaf(r, s.z + bn, gn));
            hprev = fmaf(z, hprev - n, n);   // (1-z)*n + z*h
            h_s[tid] = hprev;
        }
        __syncthreads();
    }

    // out = h @ final_w.T + final_b   (3 outputs)
    if (tid < 32) {
#pragma unroll
        for (int o = 0; o < 3; o++) {
            float acc = 0.0f;
#pragma unroll
            for (int i = 0; i < 4; i++)
                acc = fmaf(fw[o * S + tid + 32 * i], h_s[tid + 32 * i], acc);
#pragma unroll
            for (int m = 16; m >= 1; m >>= 1)
                acc += __shfl_xor_sync(0xffffffffu, acc, m);
            if (tid == 0) out[o] = acc + fb[o];
        }
    }
}

// ---------------------------------------------------------------------------
extern "C" void kernel_launch(void* const* d_in, const int* in_sizes, int n_in,
                              void* d_out, int out_size)
{
    (void)in_sizes; (void)n_in; (void)out_size;
    const float* evs    = (const float*)d_in[0];
    const float* h0     = (const float*)d_in[1];
    const float* w_ih   = (const float*)d_in[2];
    const float* w_hh   = (const float*)d_in[3];
    const float* b_ih   = (const float*)d_in[4];
    const float* b_hh   = (const float*)d_in[5];
    const float* proj_w = (const float*)d_in[6];
    const float* proj_b = (const float*)d_in[7];
    const float* fw     = (const float*)d_in[8];
    const float* fb     = (const float*)d_in[9];

    proj_kernel<<<dim3(2, 128), 256>>>(evs, proj_w, proj_b);
    ih_kernel<<<dim3(6, 128), 256>>>(w_ih, b_ih);
    gru_scan_kernel<<<1, 512>>>(w_hh, b_hh, h0, fw, fb, (float*)d_out);
}

// round 2
// speedup vs baseline: 1.0013x; 1.0013x over previous
#include <cuda_runtime.h>
#include <cstdint>

#define N_SEQ 16384
#define S 128

// Scratch (device globals: allocation-free per harness rules)
__device__ float g_x[N_SEQ * S];        // 8 MB
__device__ float g_gi[N_SEQ * 3 * S];   // 25 MB

// ---------------------------------------------------------------------------
// fast-math helpers (MUFU-backed)
// ---------------------------------------------------------------------------
__device__ __forceinline__ float ex2f(float x) {
    float y; asm("ex2.approx.f32 %0, %1;" : "=f"(y) : "f"(x)); return y;
}
__device__ __forceinline__ float rcpf(float x) {
    float y; asm("rcp.approx.f32 %0, %1;" : "=f"(y) : "f"(x)); return y;
}
__device__ __forceinline__ float sigmoidf_(float x) {
    // 1/(1+exp(-x)) = rcp(1 + 2^(-x*log2e))
    return rcpf(1.0f + ex2f(-1.4426950408889634f * x));
}
__device__ __forceinline__ float tanhf_(float x) {
    // tanh(x) = 2*sigmoid(2x) - 1
    return fmaf(2.0f, rcpf(1.0f + ex2f(-2.8853900817779268f * x)), -1.0f);
}

// ---------------------------------------------------------------------------
// packed f32x2 FMA (Blackwell): 2 lane-FMAs per issue
// ---------------------------------------------------------------------------
__device__ __forceinline__ unsigned long long pack2(float a, float b) {
    unsigned long long r;
    asm("mov.b64 %0, {%1, %2};" : "=l"(r) : "f"(a), "f"(b));
    return r;
}
__device__ __forceinline__ void fma2(unsigned long long& d,
                                     unsigned long long a, unsigned long long b) {
    asm("fma.rn.f32x2 %0, %1, %2, %0;" : "+l"(d) : "l"(a), "l"(b));
}
__device__ __forceinline__ float2 unpack2(unsigned long long v) {
    float lo, hi;
    asm("mov.b64 {%0, %1}, %2;" : "=f"(lo), "=f"(hi) : "l"(v));
    return make_float2(lo, hi);
}

// ---------------------------------------------------------------------------
// Prelude: Y[n][j] = dot(X[n], W[j]) + b[j]   (W rows are length 128)
// maskcol >= 0: that output column is the one-hot mask (1 at row 0) instead.
// 256 threads/block; block covers a 64-wide j-tile x 128-row tile.
// ---------------------------------------------------------------------------
__device__ __forceinline__ void dense_body(
    const float* __restrict__ X, const float* __restrict__ W,
    const float* __restrict__ b, float* __restrict__ Y,
    int J, int maskcol)
{
    __shared__ float wt[64 * 132];
    __shared__ float bs[64];
    __shared__ __align__(16) float xs[2][S];

    const int jbase = blockIdx.x * 64;
    const int rbase = blockIdx.y * 128;

    for (int idx = threadIdx.x; idx < 64 * S; idx += 256) {
        int j = idx >> 7, k = idx & 127;
        int gj = jbase + j;
        float v = 0.0f;
        if (gj < J && gj != maskcol) v = W[gj * S + k];
        wt[j * 132 + k] = v;
    }
    if (threadIdx.x < 64) {
        int gj = jbase + threadIdx.x;
        bs[threadIdx.x] = (gj < J && gj != maskcol) ? b[gj] : 0.0f;
    }
    __syncthreads();

    const int j = threadIdx.x >> 2;   // 0..63
    const int q = threadIdx.x & 3;    // k-quarter (strided k = 4i+q: conflict-free)

    for (int r0 = 0; r0 < 128; r0 += 2) {
        {
            int rr = threadIdx.x >> 7, k = threadIdx.x & 127;
            xs[rr][k] = X[(rbase + r0 + rr) * S + k];
        }
        __syncthreads();

        float a0 = 0.0f, a1 = 0.0f;
#pragma unroll
        for (int i = 0; i < 32; i++) {
            int k = 4 * i + q;
            float w = wt[j * 132 + k];
            a0 = fmaf(w, xs[0][k], a0);
            a1 = fmaf(w, xs[1][k], a1);
        }
        a0 += __shfl_xor_sync(0xffffffffu, a0, 1);
        a0 += __shfl_xor_sync(0xffffffffu, a0, 2);
        a1 += __shfl_xor_sync(0xffffffffu, a1, 1);
        a1 += __shfl_xor_sync(0xffffffffu, a1, 2);

        if (q == 0) {
            int gj = jbase + j;
            if (gj < J) {
                int row0 = rbase + r0;
                float v0 = a0 + bs[j];
                float v1 = a1 + bs[j];
                if (gj == maskcol) { v0 = (row0 == 0) ? 1.0f : 0.0f; v1 = 0.0f; }
                Y[row0 * J + gj]       = v0;
                Y[(row0 + 1) * J + gj] = v1;
            }
        }
        __syncthreads();
    }
}

__global__ void proj_kernel(const float* __restrict__ evs,
                            const float* __restrict__ proj_w,
                            const float* __restrict__ proj_b)
{
    dense_body(evs, proj_w, proj_b, g_x, S, 127);
}

__global__ void ih_kernel(const float* __restrict__ w_ih,
                          const float* __restrict__ b_ih)
{
    dense_body(g_x, w_ih, b_ih, g_gi, 3 * S, -1);
}

// ---------------------------------------------------------------------------
// The sequential GRU scan. One CTA, 512 threads.
// Thread (u = tid>>2, q = tid&3) owns W_hh rows {u, 128+u, 256+u},
// k in [32q, 32q+32), held in registers as 48 packed f32x2 values.
// ---------------------------------------------------------------------------
__global__ void __launch_bounds__(512, 1)
gru_scan_kernel(const float* __restrict__ w_hh, const float* __restrict__ b_hh,
                const float* __restrict__ h0,   const float* __restrict__ fw,
                const float* __restrict__ fb,   float* __restrict__ out)
{
    __shared__ __align__(16) float  h_s[S];
    __shared__ __align__(16) float4 gh4[S];

    const int tid = threadIdx.x;
    const int u = tid >> 2;
    const int q = tid & 3;

    // W_hh slice -> registers (packed pairs)
    unsigned long long w0[16], w1[16], w2[16];
    const float2* Wr = reinterpret_cast<const float2*>(w_hh);  // 64 float2 per row
#pragma unroll
    for (int i = 0; i < 16; i++) {
        float2 a = Wr[(u)         * 64 + q * 16 + i];
        float2 c = Wr[(S + u)     * 64 + q * 16 + i];
        float2 d = Wr[(2 * S + u) * 64 + q * 16 + i];
        w0[i] = pack2(a.x, a.y);
        w1[i] = pack2(c.x, c.y);
        w2[i] = pack2(d.x, d.y);
    }

    float br = 0.0f, bz = 0.0f, bn = 0.0f, hprev = 0.0f;
    if (tid < S) {
        br = b_hh[tid];
        bz = b_hh[S + tid];
        bn = b_hh[2 * S + tid];
        hprev = h0[tid];
        h_s[tid] = hprev;
    }
    __syncthreads();

    const unsigned long long* h8 = reinterpret_cast<const unsigned long long*>(h_s);
    const float* __restrict__ gi = g_gi;

    for (int t = 0; t < N_SEQ; t++) {
        // Prefetch this step's input projections (latency hidden under matvec).
        float gr = 0.0f, gz = 0.0f, gn = 0.0f;
        if (tid < S) {
            const float* gp = gi + t * (3 * S) + tid;
            gr = __ldg(gp);
            gz = __ldg(gp + S);
            gn = __ldg(gp + 2 * S);
        }

        // matvec: gh = W_hh @ h (partial over this thread's 32 k's, 3 rows)
        unsigned long long a0 = 0ull, a1 = 0ull, a2 = 0ull;
#pragma unroll
        for (int i = 0; i < 8; i++) {
            unsigned long long hA = h8[q * 16 + 2 * i];
            unsigned long long hB = h8[q * 16 + 2 * i + 1];
            fma2(a0, w0[2 * i], hA); fma2(a0, w0[2 * i + 1], hB);
            fma2(a1, w1[2 * i], hA); fma2(a1, w1[2 * i + 1], hB);
            fma2(a2, w2[2 * i], hA); fma2(a2, w2[2 * i + 1], hB);
        }
        float2 f0 = unpack2(a0), f1 = unpack2(a1), f2 = unpack2(a2);
        float rs = f0.x + f0.y;
        float zs = f1.x + f1.y;
        float ns = f2.x + f2.y;
        // reduce across the 4 adjacent q-lanes
        rs += __shfl_xor_sync(0xffffffffu, rs, 1);
        rs += __shfl_xor_sync(0xffffffffu, rs, 2);
        zs += __shfl_xor_sync(0xffffffffu, zs, 1);
        zs += __shfl_xor_sync(0xffffffffu, zs, 2);
        ns += __shfl_xor_sync(0xffffffffu, ns, 1);
        ns += __shfl_xor_sync(0xffffffffu, ns, 2);
        if (q == 0) gh4[u] = make_float4(rs, zs, ns, 0.0f);
        __syncthreads();

        // gates: warps 0-3 only (one per SMSP -> MUFU spread)
        if (tid < S) {
            float4 s = gh4[tid];
            float r = sigmoidf_(gr + s.x + br);
            float z = sigmoidf_(gz + s.y + bz);
            float n = tanhf_(fmaf(r, s.z + bn, gn));
            hprev = fmaf(z, hprev - n, n);   // (1-z)*n + z*h
            h_s[tid] = hprev;
        }
        __syncthreads();
    }

    // out = h @ final_w.T + final_b   (3 outputs)
    if (tid < 32) {
#pragma unroll
        for (int o = 0; o < 3; o++) {
            float acc = 0.0f;
#pragma unroll
            for (int i = 0; i < 4; i++)
                acc = fmaf(fw[o * S + tid + 32 * i], h_s[tid + 32 * i], acc);
#pragma unroll
            for (int m = 16; m >= 1; m >>= 1)
                acc += __shfl_xor_sync(0xffffffffu, acc, m);
            if (tid == 0) out[o] = acc + fb[o];
        }
    }
}

// ---------------------------------------------------------------------------
extern "C" void kernel_launch(void* const* d_in, const int* in_sizes, int n_in,
                              void* d_out, int out_size)
{
    (void)in_sizes; (void)n_in; (void)out_size;
    const float* evs    = (const float*)d_in[0];
    const float* h0     = (const float*)d_in[1];
    const float* w_ih   = (const float*)d_in[2];
    const float* w_hh   = (const float*)d_in[3];
    const float* b_ih   = (const float*)d_in[4];
    const float* b_hh   = (const float*)d_in[5];
    const float* proj_w = (const float*)d_in[6];
    const float* proj_b = (const float*)d_in[7];
    const float* fw     = (const float*)d_in[8];
    const float* fb     = (const float*)d_in[9];

    proj_kernel<<<dim3(2, 128), 256>>>(evs, proj_w, proj_b);
    ih_kernel<<<dim3(6, 128), 256>>>(w_ih, b_ih);
    gru_scan_kernel<<<1, 512>>>(w_hh, b_hh, h0, fw, fb, (float*)d_out);
}